// round 11
// baseline (speedup 1.0000x reference)
#include <cuda_runtime.h>
#include <cuda_fp16.h>
#include <cstdint>
#include <cmath>

// Problem dims
#define NB   4096
#define DOBS 256
#define DH   1024
#define DOUT 256
#define NTT  20

// GEMM tile config: 256 thr, 8 warps (2M x 4N), warp tile 64x64, fp16
// BK=32, 4-stage cp.async ring (2 tiles in flight) to hide L2 latency at occ=1.
#define BM 128
#define BN 256
#define BK 32
#define NSTAGE 4
#define A_STAGE_B (BM * BK * 2)   // 8192 bytes  (128 rows x 64B)
#define B_STAGE_B (BN * BK * 2)   // 16384 bytes (256 rows x 64B, n-major)
#define STAGE_B   (A_STAGE_B + B_STAGE_B)        // 24576
#define SMEM_TOTAL (NSTAGE * STAGE_B)            // 98304

// Epilogue modes
//  0: out1(f32) = v + bias[col]
//  1: out1(f16) = tanh(v + bias[col])
//  2: k=v+bias; out1(f32) acc = hb+ca*k; out2(f16) arg = hb+cb*k
//  3: k=v+bias; out1(f32) acc += ca*k;  out2(f16) arg = hb+cb*k
//  4: k=v+bias; out1(f32) hcur = accIn+ca*k; out2(f16) = same
//  5: out1(f32) = sigmoid(v + xw)
//  6: ct=sigmoid(v+xw); cn=g*(c+ct); hn=g*tanh(cn); out1(f32)=cn, out2(f32)=hn, out3(f16)=hn
struct EpiParams {
    const float* bias;
    const float* tgrid;
    int   step;
    float fa, fb;
    const float* aux1;
    const float* aux2;
    const float* aux3;
    float* out1;
    void*  out2;
    void*  out3;
    int mode;
};

// Scratch (device globals — no allocation allowed)
__device__ __align__(128) float  g_xw   [(size_t)NB * DH];
__device__ __align__(128) float  g_gate [(size_t)NB * DH];
__device__ __align__(128) float  g_hcur [(size_t)NB * DH];
__device__ __align__(128) float  g_acc  [(size_t)NB * DH];
__device__ __align__(128) __half g_u    [(size_t)NB * DH];
__device__ __align__(128) __half g_arg  [(size_t)NB * DH];
__device__ __align__(128) __half g_hbuf [(size_t)NB * DH];
__device__ __align__(128) __half g_hcurH[(size_t)NB * DH];
__device__ __align__(128) __half g_xH   [(size_t)NB * DOBS];
__device__ __align__(128) __half g_hH   [(size_t)NB * DH];
// Transposed fp16 weights, [N, K] layout
__device__ __align__(128) __half g_wi2hT[(size_t)DH * (DOBS + DH)];  // [1024, 1280]
__device__ __align__(128) __half g_wf1T [(size_t)DH * DH];
__device__ __align__(128) __half g_wf2T [(size_t)DH * DH];
__device__ __align__(128) __half g_wh2oT[(size_t)DOUT * DH];         // [256, 1024]

__device__ __forceinline__ uint32_t smem_u32(const void* p) {
    uint32_t a;
    asm("{ .reg .u64 t; cvta.to.shared.u64 t, %1; cvt.u32.u64 %0, t; }"
        : "=r"(a) : "l"(p));
    return a;
}

__device__ __forceinline__ void cpa16(uint32_t s, const void* g) {
    asm volatile("cp.async.cg.shared.global [%0], [%1], 16;" :: "r"(s), "l"(g));
}
__device__ __forceinline__ void cpa_commit() {
    asm volatile("cp.async.commit_group;" ::: "memory");
}
__device__ __forceinline__ void cpa_wait0() {
    asm volatile("cp.async.wait_group 0;" ::: "memory");
}
__device__ __forceinline__ void cpa_wait1() {
    asm volatile("cp.async.wait_group 1;" ::: "memory");
}
__device__ __forceinline__ void cpa_wait2() {
    asm volatile("cp.async.wait_group 2;" ::: "memory");
}

__device__ __forceinline__ void ldsm_x4(uint32_t& r0, uint32_t& r1, uint32_t& r2,
                                        uint32_t& r3, uint32_t addr) {
    asm volatile("ldmatrix.sync.aligned.m8n8.x4.shared.b16 {%0,%1,%2,%3}, [%4];"
                 : "=r"(r0), "=r"(r1), "=r"(r2), "=r"(r3) : "r"(addr));
}

__device__ __forceinline__ void mma_f16(float c[4], const uint32_t a[4], const uint32_t b[2]) {
    asm volatile(
        "mma.sync.aligned.m16n8k16.row.col.f32.f16.f16.f32 "
        "{%0,%1,%2,%3}, {%4,%5,%6,%7}, {%8,%9}, {%0,%1,%2,%3};"
        : "+f"(c[0]), "+f"(c[1]), "+f"(c[2]), "+f"(c[3])
        : "r"(a[0]), "r"(a[1]), "r"(a[2]), "r"(a[3]), "r"(b[0]), "r"(b[1]));
}

__device__ __forceinline__ float sigm(float x) { return 1.f / (1.f + expf(-x)); }

// 64B-row swizzle: chunk c (16B units, 0..3) at row r maps to c' = (c + (r>>1)) & 3.
// Banks (4r + c') mod 8 are distinct across any aligned 8-row LDSM group.
__device__ __forceinline__ uint32_t sw_off(int r, int c) {
    return (uint32_t)(r * 64) + ((uint32_t)((c + (r >> 1)) & 3) << 4);
}

// ---------------------------------------------------------------------------
// Prep kernel 1: x + h fp32 -> fp16 (single launch)
// ---------------------------------------------------------------------------
__global__ void cvt_inputs(const float* __restrict__ x, const float* __restrict__ h,
                           __half* __restrict__ xH, __half* __restrict__ hH) {
    int i = (blockIdx.x * blockDim.x + threadIdx.x) * 4;
    const int nx = NB * DOBS;
    const float* in; __half* outp; int j;
    if (i < nx) { in = x; outp = xH; j = i; }
    else        { in = h; outp = hH; j = i - nx; }
    float4 v = *(const float4*)(in + j);
    *(__half2*)(outp + j)     = __floats2half2_rn(v.x, v.y);
    *(__half2*)(outp + j + 2) = __floats2half2_rn(v.z, v.w);
}

// ---------------------------------------------------------------------------
// Prep kernel 2: all 4 weight transposes (blockIdx.z selects the tensor)
// W[K,N] fp32 -> WT[N,K] fp16
// ---------------------------------------------------------------------------
__global__ void transpose_all(
    const float* __restrict__ W0, const float* __restrict__ W1,
    const float* __restrict__ W2, const float* __restrict__ W3,
    __half* __restrict__ T0, __half* __restrict__ T1,
    __half* __restrict__ T2, __half* __restrict__ T3)
{
    const float* W; __half* T; int K, N;
    switch (blockIdx.z) {
        case 0:  W = W0; T = T0; K = DOBS + DH; N = DH;   break;
        case 1:  W = W1; T = T1; K = DH;        N = DH;   break;
        case 2:  W = W2; T = T2; K = DH;        N = DH;   break;
        default: W = W3; T = T3; K = DH;        N = DOUT; break;
    }
    int n0 = blockIdx.x * 32, k0 = blockIdx.y * 32;
    if (n0 >= N || k0 >= K) return;
    __shared__ float tile[32][33];
    int tx = threadIdx.x, ty = threadIdx.y;  // 32 x 8
    #pragma unroll
    for (int i = 0; i < 32; i += 8)
        tile[ty + i][tx] = W[(size_t)(k0 + ty + i) * N + n0 + tx];
    __syncthreads();
    #pragma unroll
    for (int i = 0; i < 32; i += 8) {
        float v = tile[tx][ty + i];
        T[(size_t)(n0 + ty + i) * K + k0 + tx] = __float2half_rn(v);
    }
}

// ---------------------------------------------------------------------------
// Pipelined fp16 mma.sync GEMM (m16n8k16), 64x64 warp tiles, ldmatrix,
// 4-stage cp.async ring with 2 tiles in flight.
// ---------------------------------------------------------------------------
__global__ __launch_bounds__(256, 1) void gemm_epi(
    const __half* __restrict__ A, const __half* __restrict__ WT,
    int K, int ldw, int N, EpiParams ep)
{
    extern __shared__ char smem_raw[];
    const uint32_t s0 = smem_u32(smem_raw);

    const int m0 = blockIdx.y * BM;
    const int n0 = blockIdx.x * BN;
    const int tid  = threadIdx.x;
    const int lane = tid & 31;
    const int wid  = tid >> 5;
    const int wm = (wid & 1) * 64;   // 2 warps along M
    const int wn = (wid >> 1) * 64;  // 4 warps along N

    // Loader coords: chunks of 16B; id -> row = id>>2, chunk = id&3
    const int lr = tid >> 2, lc = tid & 3;   // base: rows 0..63

    const __half* Abase = A + (size_t)m0 * K;
    const __half* Bbase = WT + (size_t)n0 * ldw;

    // LDSM per-lane coords
    const int q  = lane >> 3;
    const int rr = lane & 7;
    const int cbA = q >> 1;          // A k-half within k16
    const int cbB = q & 1;           // B k-half within k16
    int mArow[4];
    #pragma unroll
    for (int mt = 0; mt < 4; mt++) mArow[mt] = wm + mt * 16 + ((q & 1) << 3) + rr;
    int nBrow[4];
    #pragma unroll
    for (int p = 0; p < 4; p++) nBrow[p] = wn + p * 16 + ((q >> 1) << 3) + rr;

    float accr[4][8][4];
    #pragma unroll
    for (int i = 0; i < 4; i++)
        #pragma unroll
        for (int j = 0; j < 8; j++)
            #pragma unroll
            for (int k = 0; k < 4; k++) accr[i][j][k] = 0.f;

    const int KT = K / BK;

    auto issue_tile = [&](int kt, int st) {
        const uint32_t sa = s0 + st * STAGE_B;
        const uint32_t sb = sa + A_STAGE_B;
        const __half* Ab = Abase + (size_t)kt * BK;
        const __half* Bb = Bbase + (size_t)kt * BK;
        // A: 128 rows x 4 chunks = 512 chunks, 2 per thread
        #pragma unroll
        for (int i = 0; i < 2; i++) {
            int r = lr + i * 64;
            cpa16(sa + sw_off(r, lc), Ab + (size_t)r * K + lc * 8);
        }
        // B: 256 rows x 4 chunks = 1024 chunks, 4 per thread
        #pragma unroll
        for (int i = 0; i < 4; i++) {
            int r = lr + i * 64;
            cpa16(sb + sw_off(r, lc), Bb + (size_t)r * ldw + lc * 8);
        }
        cpa_commit();
    };

    // Prologue: 3 tiles ahead
    issue_tile(0, 0);
    if (KT > 1) issue_tile(1, 1);
    if (KT > 2) issue_tile(2, 2);

    for (int kt = 0; kt < KT; kt++) {
        // Ensure tile kt landed; keep up to 2 newer groups in flight
        if (kt + 3 <= KT)      cpa_wait2();
        else if (kt + 2 <= KT) cpa_wait1();
        else                   cpa_wait0();
        __syncthreads();
        if (kt + 3 < KT) {
            int st3 = (kt + 3) & (NSTAGE - 1);
            issue_tile(kt + 3, st3);
        }

        const int st = kt & (NSTAGE - 1);
        const uint32_t sa = s0 + st * STAGE_B;
        const uint32_t sb = sa + A_STAGE_B;

        #pragma unroll
        for (int ks = 0; ks < 2; ks++) {   // 2 k16 steps per BK=32 tile
            // A fragments: 4 ldmatrix.x4 (one per m16 tile)
            uint32_t af[4][4];
            #pragma unroll
            for (int mt = 0; mt < 4; mt++) {
                int m = mArow[mt];
                ldsm_x4(af[mt][0], af[mt][1], af[mt][2], af[mt][3],
                        sa + sw_off(m, 2 * ks + cbA));
            }
            // B fragments: 4 ldmatrix.x4, each covering two n8 tiles
            uint32_t bf[8][2];
            #pragma unroll
            for (int p = 0; p < 4; p++) {
                int n = nBrow[p];
                ldsm_x4(bf[2 * p][0], bf[2 * p][1], bf[2 * p + 1][0], bf[2 * p + 1][1],
                        sb + sw_off(n, 2 * ks + cbB));
            }
            #pragma unroll
            for (int mt = 0; mt < 4; mt++)
                #pragma unroll
                for (int nt = 0; nt < 8; nt++)
                    mma_f16(accr[mt][nt], af[mt], bf[nt]);
        }
    }

    // ---------------- Epilogue ----------------
    float ca = 0.f, cb = 0.f;
    if (ep.mode >= 2 && ep.mode <= 4) {
        float dt = ep.tgrid[ep.step + 1] - ep.tgrid[ep.step];
        ca = ep.fa * dt;
        cb = ep.fb * dt;
    }

    #pragma unroll
    for (int mt = 0; mt < 4; mt++)
        #pragma unroll
        for (int nt = 0; nt < 8; nt++)
            #pragma unroll
            for (int hf = 0; hf < 2; hf++) {
                const int row = m0 + wm + mt * 16 + (lane >> 2) + hf * 8;
                const int col = n0 + wn + nt * 8 + ((lane & 3) << 1);
                const size_t idx = (size_t)row * N + col;
                float v0 = accr[mt][nt][hf * 2 + 0];
                float v1 = accr[mt][nt][hf * 2 + 1];
                float2 r1, r2;
                switch (ep.mode) {
                    case 0: {
                        float2 b = *(const float2*)(ep.bias + col);
                        r1.x = v0 + b.x; r1.y = v1 + b.y;
                        *(float2*)(ep.out1 + idx) = r1;
                    } break;
                    case 1: {
                        float2 b = *(const float2*)(ep.bias + col);
                        *(__half2*)((__half*)ep.out1 + idx) =
                            __floats2half2_rn(tanhf(v0 + b.x), tanhf(v1 + b.y));
                    } break;
                    case 2: {
                        float2 b = *(const float2*)(ep.bias + col);
                        float2 hb = *(const float2*)(ep.aux1 + idx);
                        float k0 = v0 + b.x, k1 = v1 + b.y;
                        r1.x = hb.x + ca * k0; r1.y = hb.y + ca * k1;
                        *(float2*)(ep.out1 + idx) = r1;
                        *(__half2*)((__half*)ep.out2 + idx) =
                            __floats2half2_rn(hb.x + cb * k0, hb.y + cb * k1);
                    } break;
                    case 3: {
                        float2 b = *(const float2*)(ep.bias + col);
                        float2 hb = *(const float2*)(ep.aux1 + idx);
                        float2 aa = *(const float2*)(ep.out1 + idx);
                        float k0 = v0 + b.x, k1 = v1 + b.y;
                        r1.x = aa.x + ca * k0; r1.y = aa.y + ca * k1;
                        *(float2*)(ep.out1 + idx) = r1;
                        *(__half2*)((__half*)ep.out2 + idx) =
                            __floats2half2_rn(hb.x + cb * k0, hb.y + cb * k1);
                    } break;
                    case 4: {
                        float2 b = *(const float2*)(ep.bias + col);
                        float2 aa = *(const float2*)(ep.aux1 + idx);
                        float h0 = aa.x + ca * (v0 + b.x);
                        float h1 = aa.y + ca * (v1 + b.y);
                        r1.x = h0; r1.y = h1;
                        *(float2*)(ep.out1 + idx) = r1;
                        *(__half2*)((__half*)ep.out2 + idx) = __floats2half2_rn(h0, h1);
                    } break;
                    case 5: {
                        float2 xw2 = *(const float2*)(ep.aux1 + idx);
                        r1.x = sigm(v0 + xw2.x); r1.y = sigm(v1 + xw2.y);
                        *(float2*)(ep.out1 + idx) = r1;
                    } break;
                    case 6: {
                        float2 xw2 = *(const float2*)(ep.aux1 + idx);
                        float2 g2  = *(const float2*)(ep.aux2 + idx);
                        float2 c2  = *(const float2*)(ep.aux3 + idx);
                        float ct0 = sigm(v0 + xw2.x), ct1 = sigm(v1 + xw2.y);
                        float cn0 = g2.x * (c2.x + ct0), cn1 = g2.y * (c2.y + ct1);
                        float hn0 = g2.x * tanhf(cn0), hn1 = g2.y * tanhf(cn1);
                        r1.x = cn0; r1.y = cn1;
                        r2.x = hn0; r2.y = hn1;
                        *(float2*)(ep.out1 + idx) = r1;
                        *(float2*)((float*)ep.out2 + idx) = r2;
                        *(__half2*)((__half*)ep.out3 + idx) = __floats2half2_rn(hn0, hn1);
                    } break;
                }
            }
}

// ---------------------------------------------------------------------------
// Host orchestration
// ---------------------------------------------------------------------------
static inline void run_gemm(const __half* A, const __half* WT, int K, int ldw, int N,
                            const EpiParams& ep) {
    dim3 grid(N / BN, NB / BM), blk(256);
    gemm_epi<<<grid, blk, SMEM_TOTAL>>>(A, WT, K, ldw, N, ep);
}

extern "C" void kernel_launch(void* const* d_in, const int* in_sizes, int n_in,
                              void* d_out, int out_size) {
    const float* x     = (const float*)d_in[0];
    const float* h     = (const float*)d_in[1];
    const float* c     = (const float*)d_in[2];
    const float* t     = (const float*)d_in[3];
    const float* W_i2h = (const float*)d_in[4];
    const float* b_i2h = (const float*)d_in[5];
    const float* W_h2o = (const float*)d_in[6];
    const float* b_h2o = (const float*)d_in[7];
    const float* Wf1   = (const float*)d_in[8];
    const float* bf1   = (const float*)d_in[9];
    const float* Wf2   = (const float*)d_in[10];
    const float* bf2   = (const float*)d_in[11];

    float* out   = (float*)d_out;
    float* out_o = out;
    float* out_h = out + (size_t)NB * DOUT;
    float* out_c = out + (size_t)NB * DOUT + (size_t)NB * DH;

    cudaFuncSetAttribute(gemm_epi, cudaFuncAttributeMaxDynamicSharedMemorySize, SMEM_TOTAL);

    float *xw, *gate, *hcur, *acc;
    __half *u, *arg, *hbuf, *hcurH, *xH, *hH;
    __half *wi2hT, *wf1T, *wf2T, *wh2oT;
    cudaGetSymbolAddress((void**)&xw,    g_xw);
    cudaGetSymbolAddress((void**)&gate,  g_gate);
    cudaGetSymbolAddress((void**)&hcur,  g_hcur);
    cudaGetSymbolAddress((void**)&acc,   g_acc);
    cudaGetSymbolAddress((void**)&u,     g_u);
    cudaGetSymbolAddress((void**)&arg,   g_arg);
    cudaGetSymbolAddress((void**)&hbuf,  g_hbuf);
    cudaGetSymbolAddress((void**)&hcurH, g_hcurH);
    cudaGetSymbolAddress((void**)&xH,    g_xH);
    cudaGetSymbolAddress((void**)&hH,    g_hH);
    cudaGetSymbolAddress((void**)&wi2hT, g_wi2hT);
    cudaGetSymbolAddress((void**)&wf1T,  g_wf1T);
    cudaGetSymbolAddress((void**)&wf2T,  g_wf2T);
    cudaGetSymbolAddress((void**)&wh2oT, g_wh2oT);

    // Prep (2 launches)
    cvt_inputs<<<(NB * (DOBS + DH)) / 1024, 256>>>(x, h, xH, hH);
    {
        dim3 blk(32, 8);
        transpose_all<<<dim3(32, 40, 4), blk>>>(W_i2h, Wf1, Wf2, W_h2o,
                                                wi2hT, wf1T, wf2T, wh2oT);
    }

    const int LDW = DOBS + DH;               // 1280: row stride of wi2hT
    const __half* wbotT = wi2hT + DOBS;      // k-offset 256 within each row

    // 1) xw = x @ W_i2h[:256] + b_i2h
    {
        EpiParams ep{}; ep.bias = b_i2h; ep.out1 = xw; ep.mode = 0;
        run_gemm(xH, wi2hT, DOBS, LDW, DH, ep);
    }
    // 2) gate = sigmoid(xw + h @ W_bot)
    {
        EpiParams ep{}; ep.aux1 = xw; ep.out1 = gate; ep.mode = 5;
        run_gemm(hH, wbotT, DH, LDW, DH, ep);
    }
    // 3) RK4
    for (int s = 0; s < NTT - 1; s++) {
        const __half* hbH = (s == 0) ? hH : hcurH;
        const float*  hb  = (s == 0) ? h  : hcur;
        // stage 1: u = tanh(hb@Wf1 + b)
        { EpiParams ep{}; ep.bias = bf1; ep.out1 = (float*)u; ep.mode = 1;
          run_gemm(hbH, wf1T, DH, DH, DH, ep); }
        { EpiParams ep{}; ep.bias = bf2; ep.tgrid = t; ep.step = s;
          ep.fa = 1.f / 6.f; ep.fb = 0.5f; ep.aux1 = hb;
          ep.out1 = acc; ep.out2 = arg; ep.mode = 2;
          run_gemm(u, wf2T, DH, DH, DH, ep); }
        // stage 2
        { EpiParams ep{}; ep.bias = bf1; ep.out1 = (float*)u; ep.mode = 1;
          run_gemm(arg, wf1T, DH, DH, DH, ep); }
        { EpiParams ep{}; ep.bias = bf2; ep.tgrid = t; ep.step = s;
          ep.fa = 1.f / 3.f; ep.fb = 0.5f; ep.aux1 = hb;
          ep.out1 = acc; ep.out2 = arg; ep.mode = 3;
          run_gemm(u, wf2T, DH, DH, DH, ep); }
        // stage 3
        { EpiParams ep{}; ep.bias = bf1; ep.out1 = (float*)u; ep.mode = 1;
          run_gemm(arg, wf1T, DH, DH, DH, ep); }
        { EpiParams ep{}; ep.bias = bf2; ep.tgrid = t; ep.step = s;
          ep.fa = 1.f / 3.f; ep.fb = 1.0f; ep.aux1 = hb;
          ep.out1 = acc; ep.out2 = arg; ep.mode = 3;
          run_gemm(u, wf2T, DH, DH, DH, ep); }
        // stage 4: hcur(f32) + hcurH(f16)
        { EpiParams ep{}; ep.bias = bf1; ep.out1 = (float*)u; ep.mode = 1;
          run_gemm(arg, wf1T, DH, DH, DH, ep); }
        { EpiParams ep{}; ep.bias = bf2; ep.tgrid = t; ep.step = s;
          ep.fa = 1.f / 6.f; ep.fb = 0.f; ep.aux1 = acc;
          ep.out1 = hcur; ep.out2 = hcurH; ep.mode = 4;
          run_gemm(u, wf2T, DH, DH, DH, ep); }
    }
    // 4) c_tilde + fused LSTM recombine (A = hcurH)
    {
        EpiParams ep{}; ep.aux1 = xw; ep.aux2 = gate; ep.aux3 = c;
        ep.out1 = out_c; ep.out2 = out_h; ep.out3 = hbuf; ep.mode = 6;
        run_gemm(hcurH, wbotT, DH, LDW, DH, ep);
    }
    // 5) out = h_new @ W_h2o + b_h2o
    {
        EpiParams ep{}; ep.bias = b_h2o; ep.out1 = out_o; ep.mode = 0;
        run_gemm(hbuf, wh2oT, DH, DH, DOUT, ep);
    }
}

// round 12
// speedup vs baseline: 1.3682x; 1.3682x over previous
#include <cuda_runtime.h>
#include <cuda_fp16.h>
#include <cstdint>
#include <cmath>

// Problem dims
#define NB   4096
#define DOBS 256
#define DH   1024
#define DOUT 256
#define NTT  20

// GEMM tile config: 512 thr, 16 warps (2M x 8N), warp tile 64x32, fp16, BK=64
#define BM 128
#define BN 256
#define BK 64
#define A_STAGE_B (BM * BK * 2)   // 16384 bytes (128 rows x 128B)
#define B_STAGE_B (BN * BK * 2)   // 32768 bytes (256 rows x 128B, n-major)
#define STAGE_B   (A_STAGE_B + B_STAGE_B)
#define SMEM_TOTAL (2 * STAGE_B)  // 98304

// Epilogue modes
//  0: out1(f32) = v + bias[col]
//  1: out1(f16) = tanh(v + bias[col])
//  2: k=v+bias; out1(f32) acc = hb+ca*k; out2(f16) arg = hb+cb*k
//  3: k=v+bias; out1(f32) acc += ca*k;  out2(f16) arg = hb+cb*k
//  4: k=v+bias; out1(f32) hcur = accIn+ca*k; out2(f16) = same
//  5: out1(f32) = sigmoid(v + xw)
//  6: ct=sigmoid(v+xw); cn=g*(c+ct); hn=g*tanh(cn); out1(f32)=cn, out2(f32)=hn, out3(f16)=hn
struct EpiParams {
    const float* bias;
    const float* tgrid;
    int   step;
    float fa, fb;
    const float* aux1;
    const float* aux2;
    const float* aux3;
    float* out1;
    void*  out2;
    void*  out3;
    int mode;
};

// Scratch (device globals — no allocation allowed)
__device__ __align__(128) float  g_xw   [(size_t)NB * DH];
__device__ __align__(128) float  g_gate [(size_t)NB * DH];
__device__ __align__(128) float  g_hcur [(size_t)NB * DH];
__device__ __align__(128) float  g_acc  [(size_t)NB * DH];
__device__ __align__(128) __half g_u    [(size_t)NB * DH];
__device__ __align__(128) __half g_arg  [(size_t)NB * DH];
__device__ __align__(128) __half g_hbuf [(size_t)NB * DH];
__device__ __align__(128) __half g_hcurH[(size_t)NB * DH];
__device__ __align__(128) __half g_xH   [(size_t)NB * DOBS];
__device__ __align__(128) __half g_hH   [(size_t)NB * DH];
// Transposed fp16 weights, [N, K] layout
__device__ __align__(128) __half g_wi2hT[(size_t)DH * (DOBS + DH)];  // [1024, 1280]
__device__ __align__(128) __half g_wf1T [(size_t)DH * DH];
__device__ __align__(128) __half g_wf2T [(size_t)DH * DH];
__device__ __align__(128) __half g_wh2oT[(size_t)DOUT * DH];         // [256, 1024]

__device__ __forceinline__ uint32_t smem_u32(const void* p) {
    uint32_t a;
    asm("{ .reg .u64 t; cvta.to.shared.u64 t, %1; cvt.u32.u64 %0, t; }"
        : "=r"(a) : "l"(p));
    return a;
}

__device__ __forceinline__ void cpa16(uint32_t s, const void* g) {
    asm volatile("cp.async.cg.shared.global [%0], [%1], 16;" :: "r"(s), "l"(g));
}
__device__ __forceinline__ void cpa_commit() {
    asm volatile("cp.async.commit_group;" ::: "memory");
}
__device__ __forceinline__ void cpa_wait0() {
    asm volatile("cp.async.wait_group 0;" ::: "memory");
}

__device__ __forceinline__ void ldsm_x4(uint32_t& r0, uint32_t& r1, uint32_t& r2,
                                        uint32_t& r3, uint32_t addr) {
    asm volatile("ldmatrix.sync.aligned.m8n8.x4.shared.b16 {%0,%1,%2,%3}, [%4];"
                 : "=r"(r0), "=r"(r1), "=r"(r2), "=r"(r3) : "r"(addr));
}

__device__ __forceinline__ void mma_f16(float c[4], const uint32_t a[4], const uint32_t b[2]) {
    asm volatile(
        "mma.sync.aligned.m16n8k16.row.col.f32.f16.f16.f32 "
        "{%0,%1,%2,%3}, {%4,%5,%6,%7}, {%8,%9}, {%0,%1,%2,%3};"
        : "+f"(c[0]), "+f"(c[1]), "+f"(c[2]), "+f"(c[3])
        : "r"(a[0]), "r"(a[1]), "r"(a[2]), "r"(a[3]), "r"(b[0]), "r"(b[1]));
}

__device__ __forceinline__ float sigm(float x) { return 1.f / (1.f + expf(-x)); }

// ---------------------------------------------------------------------------
// Prep kernel 1: x + h fp32 -> fp16 (single launch)
// ---------------------------------------------------------------------------
__global__ void cvt_inputs(const float* __restrict__ x, const float* __restrict__ h,
                           __half* __restrict__ xH, __half* __restrict__ hH) {
    int i = (blockIdx.x * blockDim.x + threadIdx.x) * 4;
    const int nx = NB * DOBS;
    const float* in; __half* outp; int j;
    if (i < nx) { in = x; outp = xH; j = i; }
    else        { in = h; outp = hH; j = i - nx; }
    float4 v = *(const float4*)(in + j);
    *(__half2*)(outp + j)     = __floats2half2_rn(v.x, v.y);
    *(__half2*)(outp + j + 2) = __floats2half2_rn(v.z, v.w);
}

// ---------------------------------------------------------------------------
// Prep kernel 2: all 4 weight transposes (blockIdx.z selects the tensor)
// W[K,N] fp32 -> WT[N,K] fp16
// ---------------------------------------------------------------------------
__global__ void transpose_all(
    const float* __restrict__ W0, const float* __restrict__ W1,
    const float* __restrict__ W2, const float* __restrict__ W3,
    __half* __restrict__ T0, __half* __restrict__ T1,
    __half* __restrict__ T2, __half* __restrict__ T3)
{
    const float* W; __half* T; int K, N;
    switch (blockIdx.z) {
        case 0:  W = W0; T = T0; K = DOBS + DH; N = DH;   break;
        case 1:  W = W1; T = T1; K = DH;        N = DH;   break;
        case 2:  W = W2; T = T2; K = DH;        N = DH;   break;
        default: W = W3; T = T3; K = DH;        N = DOUT; break;
    }
    int n0 = blockIdx.x * 32, k0 = blockIdx.y * 32;
    if (n0 >= N || k0 >= K) return;
    __shared__ float tile[32][33];
    int tx = threadIdx.x, ty = threadIdx.y;  // 32 x 8
    #pragma unroll
    for (int i = 0; i < 32; i += 8)
        tile[ty + i][tx] = W[(size_t)(k0 + ty + i) * N + n0 + tx];
    __syncthreads();
    #pragma unroll
    for (int i = 0; i < 32; i += 8) {
        float v = tile[tx][ty + i];
        T[(size_t)(n0 + ty + i) * K + k0 + tx] = __float2half_rn(v);
    }
}

// ---------------------------------------------------------------------------
// Pipelined fp16 mma.sync GEMM (m16n8k16), 16 warps, 64x32 warp tiles, ldmatrix.
// C[M=4096, N] (+epi) = A[4096, K] (fp16) @ WT[N, K]^T (fp16), fp32 accum.
// smem tiles: A 128 rows, B 256 rows; each row 64 halves (128B), XOR-swizzled.
// ---------------------------------------------------------------------------
__global__ __launch_bounds__(512, 1) void gemm_epi(
    const __half* __restrict__ A, const __half* __restrict__ WT,
    int K, int ldw, int N, EpiParams ep)
{
    extern __shared__ char smem_raw[];
    const uint32_t s0 = smem_u32(smem_raw);

    const int m0 = blockIdx.y * BM;
    const int n0 = blockIdx.x * BN;
    const int tid  = threadIdx.x;
    const int lane = tid & 31;
    const int wid  = tid >> 5;
    const int wm = (wid & 1) * 64;   // 2 warps along M
    const int wn = (wid >> 1) * 32;  // 8 warps along N

    // Loader coords: rows of 128B; A 1024 chunks (2/thr), B 2048 chunks (4/thr)
    const int ar = tid >> 3, ac = tid & 7;   // base rows 0..63

    const __half* Abase = A + (size_t)m0 * K;
    const __half* Bbase = WT + (size_t)n0 * ldw;

    // LDSM per-lane coords
    const int q  = lane >> 3;
    const int rr = lane & 7;
    const int cbA = q >> 1;          // A k-half within k16
    const int cbB = q & 1;           // B k-half within k16
    int mArow[4];
    #pragma unroll
    for (int mt = 0; mt < 4; mt++) mArow[mt] = wm + mt * 16 + ((q & 1) << 3) + rr;
    int nBrow[2];
    #pragma unroll
    for (int p = 0; p < 2; p++) nBrow[p] = wn + p * 16 + ((q >> 1) << 3) + rr;

    float accr[4][4][4];
    #pragma unroll
    for (int i = 0; i < 4; i++)
        #pragma unroll
        for (int j = 0; j < 4; j++)
            #pragma unroll
            for (int k = 0; k < 4; k++) accr[i][j][k] = 0.f;

    const int KT = K / BK;

    auto issue_tile = [&](int kt, int st) {
        const uint32_t sa = s0 + st * STAGE_B;
        const uint32_t sb = sa + A_STAGE_B;
        const __half* Ab = Abase + (size_t)kt * BK;
        const __half* Bb = Bbase + (size_t)kt * BK;
        // A: 128 rows x 8 chunks = 1024 chunks, 2 per thread
        #pragma unroll
        for (int i = 0; i < 2; i++) {
            int r = ar + i * 64;
            uint32_t off = (uint32_t)(r * 128) + ((uint32_t)(ac ^ (r & 7)) << 4);
            cpa16(sa + off, Ab + (size_t)r * K + ac * 8);
        }
        // B: 256 rows x 8 chunks = 2048 chunks, 4 per thread
        #pragma unroll
        for (int i = 0; i < 4; i++) {
            int r = ar + i * 64;
            uint32_t off = (uint32_t)(r * 128) + ((uint32_t)(ac ^ (r & 7)) << 4);
            cpa16(sb + off, Bb + (size_t)r * ldw + ac * 8);
        }
        cpa_commit();
    };

    issue_tile(0, 0);

    for (int kt = 0; kt < KT; kt++) {
        const int st = kt & 1;
        cpa_wait0();
        __syncthreads();
        if (kt + 1 < KT) issue_tile(kt + 1, (kt + 1) & 1);

        const uint32_t sa = s0 + st * STAGE_B;
        const uint32_t sb = sa + A_STAGE_B;

        #pragma unroll
        for (int ks = 0; ks < 4; ks++) {   // 4 k16 steps per BK=64 tile
            // A fragments: 4 ldmatrix.x4 (one per m16 tile)
            uint32_t af[4][4];
            #pragma unroll
            for (int mt = 0; mt < 4; mt++) {
                int m = mArow[mt];
                uint32_t addr = sa + (uint32_t)(m * 128)
                              + ((uint32_t)((2 * ks + cbA) ^ (m & 7)) << 4);
                ldsm_x4(af[mt][0], af[mt][1], af[mt][2], af[mt][3], addr);
            }
            // B fragments: 2 ldmatrix.x4, each covering two n8 tiles
            uint32_t bf[4][2];
            #pragma unroll
            for (int p = 0; p < 2; p++) {
                int n = nBrow[p];
                uint32_t addr = sb + (uint32_t)(n * 128)
                              + ((uint32_t)((2 * ks + cbB) ^ (n & 7)) << 4);
                ldsm_x4(bf[2 * p][0], bf[2 * p][1], bf[2 * p + 1][0], bf[2 * p + 1][1], addr);
            }
            #pragma unroll
            for (int mt = 0; mt < 4; mt++)
                #pragma unroll
                for (int nt = 0; nt < 4; nt++)
                    mma_f16(accr[mt][nt], af[mt], bf[nt]);
        }
    }

    // ---------------- Epilogue ----------------
    float ca = 0.f, cb = 0.f;
    if (ep.mode >= 2 && ep.mode <= 4) {
        float dt = ep.tgrid[ep.step + 1] - ep.tgrid[ep.step];
        ca = ep.fa * dt;
        cb = ep.fb * dt;
    }

    #pragma unroll
    for (int mt = 0; mt < 4; mt++)
        #pragma unroll
        for (int nt = 0; nt < 4; nt++)
            #pragma unroll
            for (int hf = 0; hf < 2; hf++) {
                const int row = m0 + wm + mt * 16 + (lane >> 2) + hf * 8;
                const int col = n0 + wn + nt * 8 + ((lane & 3) << 1);
                const size_t idx = (size_t)row * N + col;
                float v0 = accr[mt][nt][hf * 2 + 0];
                float v1 = accr[mt][nt][hf * 2 + 1];
                float2 r1, r2;
                switch (ep.mode) {
                    case 0: {
                        float2 b = *(const float2*)(ep.bias + col);
                        r1.x = v0 + b.x; r1.y = v1 + b.y;
                        *(float2*)(ep.out1 + idx) = r1;
                    } break;
                    case 1: {
                        float2 b = *(const float2*)(ep.bias + col);
                        *(__half2*)((__half*)ep.out1 + idx) =
                            __floats2half2_rn(tanhf(v0 + b.x), tanhf(v1 + b.y));
                    } break;
                    case 2: {
                        float2 b = *(const float2*)(ep.bias + col);
                        float2 hb = *(const float2*)(ep.aux1 + idx);
                        float k0 = v0 + b.x, k1 = v1 + b.y;
                        r1.x = hb.x + ca * k0; r1.y = hb.y + ca * k1;
                        *(float2*)(ep.out1 + idx) = r1;
                        *(__half2*)((__half*)ep.out2 + idx) =
                            __floats2half2_rn(hb.x + cb * k0, hb.y + cb * k1);
                    } break;
                    case 3: {
                        float2 b = *(const float2*)(ep.bias + col);
                        float2 hb = *(const float2*)(ep.aux1 + idx);
                        float2 aa = *(const float2*)(ep.out1 + idx);
                        float k0 = v0 + b.x, k1 = v1 + b.y;
                        r1.x = aa.x + ca * k0; r1.y = aa.y + ca * k1;
                        *(float2*)(ep.out1 + idx) = r1;
                        *(__half2*)((__half*)ep.out2 + idx) =
                            __floats2half2_rn(hb.x + cb * k0, hb.y + cb * k1);
                    } break;
                    case 4: {
                        float2 b = *(const float2*)(ep.bias + col);
                        float2 aa = *(const float2*)(ep.aux1 + idx);
                        float h0 = aa.x + ca * (v0 + b.x);
                        float h1 = aa.y + ca * (v1 + b.y);
                        r1.x = h0; r1.y = h1;
                        *(float2*)(ep.out1 + idx) = r1;
                        *(__half2*)((__half*)ep.out2 + idx) = __floats2half2_rn(h0, h1);
                    } break;
                    case 5: {
                        float2 xw2 = *(const float2*)(ep.aux1 + idx);
                        r1.x = sigm(v0 + xw2.x); r1.y = sigm(v1 + xw2.y);
                        *(float2*)(ep.out1 + idx) = r1;
                    } break;
                    case 6: {
                        float2 xw2 = *(const float2*)(ep.aux1 + idx);
                        float2 g2  = *(const float2*)(ep.aux2 + idx);
                        float2 c2  = *(const float2*)(ep.aux3 + idx);
                        float ct0 = sigm(v0 + xw2.x), ct1 = sigm(v1 + xw2.y);
                        float cn0 = g2.x * (c2.x + ct0), cn1 = g2.y * (c2.y + ct1);
                        float hn0 = g2.x * tanhf(cn0), hn1 = g2.y * tanhf(cn1);
                        r1.x = cn0; r1.y = cn1;
                        r2.x = hn0; r2.y = hn1;
                        *(float2*)(ep.out1 + idx) = r1;
                        *(float2*)((float*)ep.out2 + idx) = r2;
                        *(__half2*)((__half*)ep.out3 + idx) = __floats2half2_rn(hn0, hn1);
                    } break;
                }
            }
}

// ---------------------------------------------------------------------------
// Host orchestration
// ---------------------------------------------------------------------------
static inline void run_gemm(const __half* A, const __half* WT, int K, int ldw, int N,
                            const EpiParams& ep) {
    dim3 grid(N / BN, NB / BM), blk(512);
    gemm_epi<<<grid, blk, SMEM_TOTAL>>>(A, WT, K, ldw, N, ep);
}

extern "C" void kernel_launch(void* const* d_in, const int* in_sizes, int n_in,
                              void* d_out, int out_size) {
    const float* x     = (const float*)d_in[0];
    const float* h     = (const float*)d_in[1];
    const float* c     = (const float*)d_in[2];
    const float* t     = (const float*)d_in[3];
    const float* W_i2h = (const float*)d_in[4];
    const float* b_i2h = (const float*)d_in[5];
    const float* W_h2o = (const float*)d_in[6];
    const float* b_h2o = (const float*)d_in[7];
    const float* Wf1   = (const float*)d_in[8];
    const float* bf1   = (const float*)d_in[9];
    const float* Wf2   = (const float*)d_in[10];
    const float* bf2   = (const float*)d_in[11];

    float* out   = (float*)d_out;
    float* out_o = out;
    float* out_h = out + (size_t)NB * DOUT;
    float* out_c = out + (size_t)NB * DOUT + (size_t)NB * DH;

    cudaFuncSetAttribute(gemm_epi, cudaFuncAttributeMaxDynamicSharedMemorySize, SMEM_TOTAL);

    float *xw, *gate, *hcur, *acc;
    __half *u, *arg, *hbuf, *hcurH, *xH, *hH;
    __half *wi2hT, *wf1T, *wf2T, *wh2oT;
    cudaGetSymbolAddress((void**)&xw,    g_xw);
    cudaGetSymbolAddress((void**)&gate,  g_gate);
    cudaGetSymbolAddress((void**)&hcur,  g_hcur);
    cudaGetSymbolAddress((void**)&acc,   g_acc);
    cudaGetSymbolAddress((void**)&u,     g_u);
    cudaGetSymbolAddress((void**)&arg,   g_arg);
    cudaGetSymbolAddress((void**)&hbuf,  g_hbuf);
    cudaGetSymbolAddress((void**)&hcurH, g_hcurH);
    cudaGetSymbolAddress((void**)&xH,    g_xH);
    cudaGetSymbolAddress((void**)&hH,    g_hH);
    cudaGetSymbolAddress((void**)&wi2hT, g_wi2hT);
    cudaGetSymbolAddress((void**)&wf1T,  g_wf1T);
    cudaGetSymbolAddress((void**)&wf2T,  g_wf2T);
    cudaGetSymbolAddress((void**)&wh2oT, g_wh2oT);

    // Prep (2 launches)
    cvt_inputs<<<(NB * (DOBS + DH)) / 1024, 256>>>(x, h, xH, hH);
    {
        dim3 blk(32, 8);
        transpose_all<<<dim3(32, 40, 4), blk>>>(W_i2h, Wf1, Wf2, W_h2o,
                                                wi2hT, wf1T, wf2T, wh2oT);
    }

    const int LDW = DOBS + DH;               // 1280: row stride of wi2hT
    const __half* wbotT = wi2hT + DOBS;      // k-offset 256 within each row

    // 1) xw = x @ W_i2h[:256] + b_i2h
    {
        EpiParams ep{}; ep.bias = b_i2h; ep.out1 = xw; ep.mode = 0;
        run_gemm(xH, wi2hT, DOBS, LDW, DH, ep);
    }
    // 2) gate = sigmoid(xw + h @ W_bot)
    {
        EpiParams ep{}; ep.aux1 = xw; ep.out1 = gate; ep.mode = 5;
        run_gemm(hH, wbotT, DH, LDW, DH, ep);
    }
    // 3) RK4
    for (int s = 0; s < NTT - 1; s++) {
        const __half* hbH = (s == 0) ? hH : hcurH;
        const float*  hb  = (s == 0) ? h  : hcur;
        // stage 1: u = tanh(hb@Wf1 + b)
        { EpiParams ep{}; ep.bias = bf1; ep.out1 = (float*)u; ep.mode = 1;
          run_gemm(hbH, wf1T, DH, DH, DH, ep); }
        { EpiParams ep{}; ep.bias = bf2; ep.tgrid = t; ep.step = s;
          ep.fa = 1.f / 6.f; ep.fb = 0.5f; ep.aux1 = hb;
          ep.out1 = acc; ep.out2 = arg; ep.mode = 2;
          run_gemm(u, wf2T, DH, DH, DH, ep); }
        // stage 2
        { EpiParams ep{}; ep.bias = bf1; ep.out1 = (float*)u; ep.mode = 1;
          run_gemm(arg, wf1T, DH, DH, DH, ep); }
        { EpiParams ep{}; ep.bias = bf2; ep.tgrid = t; ep.step = s;
          ep.fa = 1.f / 3.f; ep.fb = 0.5f; ep.aux1 = hb;
          ep.out1 = acc; ep.out2 = arg; ep.mode = 3;
          run_gemm(u, wf2T, DH, DH, DH, ep); }
        // stage 3
        { EpiParams ep{}; ep.bias = bf1; ep.out1 = (float*)u; ep.mode = 1;
          run_gemm(arg, wf1T, DH, DH, DH, ep); }
        { EpiParams ep{}; ep.bias = bf2; ep.tgrid = t; ep.step = s;
          ep.fa = 1.f / 3.f; ep.fb = 1.0f; ep.aux1 = hb;
          ep.out1 = acc; ep.out2 = arg; ep.mode = 3;
          run_gemm(u, wf2T, DH, DH, DH, ep); }
        // stage 4: hcur(f32) + hcurH(f16)
        { EpiParams ep{}; ep.bias = bf1; ep.out1 = (float*)u; ep.mode = 1;
          run_gemm(arg, wf1T, DH, DH, DH, ep); }
        { EpiParams ep{}; ep.bias = bf2; ep.tgrid = t; ep.step = s;
          ep.fa = 1.f / 6.f; ep.fb = 0.f; ep.aux1 = acc;
          ep.out1 = hcur; ep.out2 = hcurH; ep.mode = 4;
          run_gemm(u, wf2T, DH, DH, DH, ep); }
    }
    // 4) c_tilde + fused LSTM recombine (A = hcurH)
    {
        EpiParams ep{}; ep.aux1 = xw; ep.aux2 = gate; ep.aux3 = c;
        ep.out1 = out_c; ep.out2 = out_h; ep.out3 = hbuf; ep.mode = 6;
        run_gemm(hcurH, wbotT, DH, LDW, DH, ep);
    }
    // 5) out = h_new @ W_h2o + b_h2o
    {
        EpiParams ep{}; ep.bias = b_h2o; ep.out1 = out_o; ep.mode = 0;
        run_gemm(hbuf, wh2oT, DH, DH, DOUT, ep);
    }
}